// round 3
// baseline (speedup 1.0000x reference)
#include <cuda_runtime.h>
#include <math.h>

#define B_ 2
#define T_ 2048
#define C_ 2048
#define H_ 16
#define D_ 128
#define M_ (B_*T_)   // 4096

// ---------------- scratch (device globals; no allocation allowed) ----------------
__device__ float g_qkv[M_ * 3 * C_];           // [4096, 6144]
__device__ float g_q[B_ * H_ * T_ * D_];       // [B,H,T,D]
__device__ float g_k[B_ * H_ * T_ * D_];
__device__ float g_v[B_ * H_ * T_ * D_];
__device__ float g_y[M_ * C_];                 // attention out, [B,T,C]

// ---------------- generic fp32 SGEMM: C[M,N] = A[M,K] @ B[K,N] -------------------
// 128x128 block tile, 8x8 per-thread micro tile, BK=8, register prefetch.
// Requires M%128==0, N%128==0, K%8==0 (true for all our shapes).
__global__ __launch_bounds__(256, 2)
void sgemm128x128(const float* __restrict__ A, const float* __restrict__ Bm,
                  float* __restrict__ Cm, int M, int N, int K) {
    __shared__ __align__(16) float As[8][132];   // transposed A tile (pad vs STS conflicts)
    __shared__ __align__(16) float Bs[8][128];

    const int tid = threadIdx.x;
    const int tn = tid & 15;
    const int tm = tid >> 4;
    const int a_row = tid >> 1;
    const int a_col = (tid & 1) * 4;
    const int b_row = tid >> 5;
    const int b_col = (tid & 31) * 4;

    const float* Ap = A + (size_t)(blockIdx.y * 128 + a_row) * K + a_col;
    const float* Bp = Bm + (size_t)b_row * N + blockIdx.x * 128 + b_col;

    float acc[8][8];
    #pragma unroll
    for (int i = 0; i < 8; i++)
        #pragma unroll
        for (int j = 0; j < 8; j++) acc[i][j] = 0.f;

    float4 aReg = *(const float4*)Ap;
    float4 bReg = *(const float4*)Bp;

    for (int kt = 0; kt < K; kt += 8) {
        As[a_col + 0][a_row] = aReg.x;
        As[a_col + 1][a_row] = aReg.y;
        As[a_col + 2][a_row] = aReg.z;
        As[a_col + 3][a_row] = aReg.w;
        *(float4*)&Bs[b_row][b_col] = bReg;
        __syncthreads();

        if (kt + 8 < K) {
            aReg = *(const float4*)(Ap + kt + 8);
            bReg = *(const float4*)(Bp + (size_t)(kt + 8) * N);
        }

        #pragma unroll
        for (int k = 0; k < 8; k++) {
            float a[8], b[8];
            *(float4*)&a[0] = *(const float4*)&As[k][tm * 8];
            *(float4*)&a[4] = *(const float4*)&As[k][tm * 8 + 4];
            *(float4*)&b[0] = *(const float4*)&Bs[k][tn * 8];
            *(float4*)&b[4] = *(const float4*)&Bs[k][tn * 8 + 4];
            #pragma unroll
            for (int i = 0; i < 8; i++)
                #pragma unroll
                for (int j = 0; j < 8; j++)
                    acc[i][j] = fmaf(a[i], b[j], acc[i][j]);
        }
        __syncthreads();
    }

    #pragma unroll
    for (int i = 0; i < 8; i++) {
        float* Cp = Cm + (size_t)(blockIdx.y * 128 + tm * 8 + i) * N
                       + blockIdx.x * 128 + tn * 8;
        *(float4*)Cp       = make_float4(acc[i][0], acc[i][1], acc[i][2], acc[i][3]);
        *(float4*)(Cp + 4) = make_float4(acc[i][4], acc[i][5], acc[i][6], acc[i][7]);
    }
}

// ---------------- RoPE + split/transpose + fold 1/sqrt(D) into Q -----------------
// one thread per (b, t, h, i) with i in [0,64): handles element pair (i, i+64)
__global__ void rope_split_kernel(const float* __restrict__ qkv,
                                  float* __restrict__ Qo, float* __restrict__ Ko,
                                  float* __restrict__ Vo) {
    int idx = blockIdx.x * blockDim.x + threadIdx.x;
    if (idx >= B_ * T_ * H_ * 64) return;
    const int i = idx & 63;
    const int h = (idx >> 6) & 15;
    const int t = (idx >> 10) & (T_ - 1);
    const int b = idx >> 21;

    const float* row = qkv + (size_t)(b * T_ + t) * (3 * C_);
    const float inv = powf(10000.f, -(float)i / 64.f);
    const float f = (float)t * inv;
    float s, c;
    sincosf(f, &s, &c);

    const float q0 = row[h * D_ + i],            q1 = row[h * D_ + i + 64];
    const float k0 = row[C_ + h * D_ + i],       k1 = row[C_ + h * D_ + i + 64];
    const float v0 = row[2 * C_ + h * D_ + i],   v1 = row[2 * C_ + h * D_ + i + 64];

    const size_t o = ((size_t)(b * H_ + h) * T_ + t) * D_ + i;
    const float sc = 0.08838834764831845f;   // 1/sqrt(128)
    Qo[o]      = (q0 * c - q1 * s) * sc;
    Qo[o + 64] = (q1 * c + q0 * s) * sc;
    Ko[o]      = k0 * c - k1 * s;
    Ko[o + 64] = k1 * c + k0 * s;
    Vo[o]      = v0;
    Vo[o + 64] = v1;
}

// ---------------- fp32 flash attention, causal, BQ=BK=128, D=128 ----------------
#define FL_SMEM_FLOATS (2 * 128 * 132 + 128 * 128)   // Qt + (Kt|Ps) + Vs = 50176

__global__ __launch_bounds__(256, 1)
void flash_attn(const float* __restrict__ Qg, const float* __restrict__ Kg,
                const float* __restrict__ Vg, float* __restrict__ Yg) {
    extern __shared__ __align__(16) float sm[];
    float* Qt   = sm;                  // Qt[d*132 + r]  (transposed)
    float* KtPs = sm + 128 * 132;      // Kt[d*132 + c]  then  Ps[r*132 + c]
    float* Vs   = sm + 2 * 128 * 132;  // Vs[c*128 + d]  (natural)

    const int tid = threadIdx.x;
    const int tn = tid & 15;           // col group
    const int tm = tid >> 4;           // row group
    const int qi = gridDim.x - 1 - blockIdx.x;   // heavy blocks first
    const int h = blockIdx.y;
    const int b = blockIdx.z;
    const size_t bh = (size_t)(b * H_ + h);
    const float* Qb = Qg + bh * T_ * D_ + (size_t)qi * 128 * D_;
    const float* Kb = Kg + bh * T_ * D_;
    const float* Vb = Vg + bh * T_ * D_;

    const int lrow = tid >> 1;
    const int c4b = (tid & 1) * 16;

    // load Q tile, transposed
    #pragma unroll
    for (int u = 0; u < 16; u++) {
        const int c4 = c4b + u;
        float4 v = *(const float4*)(Qb + lrow * D_ + c4 * 4);
        Qt[(c4 * 4 + 0) * 132 + lrow] = v.x;
        Qt[(c4 * 4 + 1) * 132 + lrow] = v.y;
        Qt[(c4 * 4 + 2) * 132 + lrow] = v.z;
        Qt[(c4 * 4 + 3) * 132 + lrow] = v.w;
    }

    float o[8][8];
    float m_i[8], l_i[8];
    #pragma unroll
    for (int i = 0; i < 8; i++) {
        m_i[i] = -INFINITY;
        l_i[i] = 0.f;
        #pragma unroll
        for (int j = 0; j < 8; j++) o[i][j] = 0.f;
    }

    for (int kt = 0; kt <= qi; kt++) {
        const float* Kt_g = Kb + (size_t)kt * 128 * D_;
        const float* Vt_g = Vb + (size_t)kt * 128 * D_;

        // K tile, transposed, into KtPs
        #pragma unroll
        for (int u = 0; u < 16; u++) {
            const int c4 = c4b + u;
            float4 v = *(const float4*)(Kt_g + lrow * D_ + c4 * 4);
            KtPs[(c4 * 4 + 0) * 132 + lrow] = v.x;
            KtPs[(c4 * 4 + 1) * 132 + lrow] = v.y;
            KtPs[(c4 * 4 + 2) * 132 + lrow] = v.z;
            KtPs[(c4 * 4 + 3) * 132 + lrow] = v.w;
        }
        // V tile, natural
        #pragma unroll
        for (int u = 0; u < 16; u++) {
            const int e = u * 256 + tid;
            const int r = e >> 5, c4 = e & 31;
            *(float4*)&Vs[r * 128 + c4 * 4] = *(const float4*)(Vt_g + r * 128 + c4 * 4);
        }
        __syncthreads();

        // S = Q @ K^T  (scale already folded into Q)
        float s[8][8];
        #pragma unroll
        for (int i = 0; i < 8; i++)
            #pragma unroll
            for (int j = 0; j < 8; j++) s[i][j] = 0.f;

        #pragma unroll 2
        for (int d = 0; d < 128; d++) {
            float a[8], bb[8];
            *(float4*)&a[0]  = *(const float4*)&Qt[d * 132 + tm * 8];
            *(float4*)&a[4]  = *(const float4*)&Qt[d * 132 + tm * 8 + 4];
            *(float4*)&bb[0] = *(const float4*)&KtPs[d * 132 + tn * 8];
            *(float4*)&bb[4] = *(const float4*)&KtPs[d * 132 + tn * 8 + 4];
            #pragma unroll
            for (int i = 0; i < 8; i++)
                #pragma unroll
                for (int j = 0; j < 8; j++)
                    s[i][j] = fmaf(a[i], bb[j], s[i][j]);
        }

        // causal mask on the diagonal tile (k-tile base == q-tile base)
        if (kt == qi) {
            #pragma unroll
            for (int i = 0; i < 8; i++)
                #pragma unroll
                for (int j = 0; j < 8; j++)
                    if (tn * 8 + j > tm * 8 + i) s[i][j] = -INFINITY;
        }

        // online softmax (rows split across the 16 tn lanes of a half-warp)
        #pragma unroll
        for (int i = 0; i < 8; i++) {
            float mx = s[i][0];
            #pragma unroll
            for (int j = 1; j < 8; j++) mx = fmaxf(mx, s[i][j]);
            #pragma unroll
            for (int off = 8; off >= 1; off >>= 1)
                mx = fmaxf(mx, __shfl_xor_sync(0xffffffffu, mx, off));
            const float mnew = fmaxf(m_i[i], mx);
            const float alpha = __expf(m_i[i] - mnew);
            m_i[i] = mnew;
            float rs = 0.f;
            #pragma unroll
            for (int j = 0; j < 8; j++) {
                s[i][j] = __expf(s[i][j] - mnew);
                rs += s[i][j];
            }
            #pragma unroll
            for (int off = 8; off >= 1; off >>= 1)
                rs += __shfl_xor_sync(0xffffffffu, rs, off);
            l_i[i] = l_i[i] * alpha + rs;
            #pragma unroll
            for (int j = 0; j < 8; j++) o[i][j] *= alpha;
        }

        __syncthreads();   // everyone done reading Kt
        // P -> smem (natural layout, reusing Kt buffer), float4 conflict-free
        #pragma unroll
        for (int i = 0; i < 8; i++) {
            float* pp = &KtPs[(tm * 8 + i) * 132 + tn * 8];
            *(float4*)pp       = make_float4(s[i][0], s[i][1], s[i][2], s[i][3]);
            *(float4*)(pp + 4) = make_float4(s[i][4], s[i][5], s[i][6], s[i][7]);
        }
        __syncthreads();

        // O += P @ V
        #pragma unroll 2
        for (int c = 0; c < 128; c++) {
            float p[8], vv[8];
            #pragma unroll
            for (int i = 0; i < 8; i++) p[i] = KtPs[(tm * 8 + i) * 132 + c];
            *(float4*)&vv[0] = *(const float4*)&Vs[c * 128 + tn * 8];
            *(float4*)&vv[4] = *(const float4*)&Vs[c * 128 + tn * 8 + 4];
            #pragma unroll
            for (int i = 0; i < 8; i++)
                #pragma unroll
                for (int j = 0; j < 8; j++)
                    o[i][j] = fmaf(p[i], vv[j], o[i][j]);
        }
        __syncthreads();   // done with Ps/Vs before next iteration overwrites
    }

    // epilogue: normalize and write to [B,T,H*D]
    #pragma unroll
    for (int i = 0; i < 8; i++) {
        const float inv = 1.0f / l_i[i];
        const int grow = qi * 128 + tm * 8 + i;
        float* yp = Yg + ((size_t)b * T_ + grow) * C_ + h * D_ + tn * 8;
        *(float4*)yp       = make_float4(o[i][0] * inv, o[i][1] * inv, o[i][2] * inv, o[i][3] * inv);
        *(float4*)(yp + 4) = make_float4(o[i][4] * inv, o[i][5] * inv, o[i][6] * inv, o[i][7] * inv);
    }
}

// ------------------------------------ launch -------------------------------------
extern "C" void kernel_launch(void* const* d_in, const int* in_sizes, int n_in,
                              void* d_out, int out_size) {
    const float* x     = (const float*)d_in[0];
    const float* w_qkv = (const float*)d_in[1];
    const float* w_out = (const float*)d_in[2];
    float* out = (float*)d_out;

    float *qkv, *q, *k, *v, *y;
    cudaGetSymbolAddress((void**)&qkv, g_qkv);
    cudaGetSymbolAddress((void**)&q, g_q);
    cudaGetSymbolAddress((void**)&k, g_k);
    cudaGetSymbolAddress((void**)&v, g_v);
    cudaGetSymbolAddress((void**)&y, g_y);

    cudaFuncSetAttribute(flash_attn, cudaFuncAttributeMaxDynamicSharedMemorySize,
                         FL_SMEM_FLOATS * (int)sizeof(float));

    // 1) qkv = x @ w_qkv            [4096,2048]x[2048,6144]
    dim3 g1(3 * C_ / 128, M_ / 128);
    sgemm128x128<<<g1, 256>>>(x, w_qkv, qkv, M_, 3 * C_, C_);

    // 2) rope + split into Q,K,V [B,H,T,D]
    const int nrope = B_ * T_ * H_ * 64;
    rope_split_kernel<<<nrope / 256, 256>>>(qkv, q, k, v);

    // 3) causal flash attention -> y [B,T,C]
    dim3 g2(T_ / 128, H_, B_);
    flash_attn<<<g2, 256, FL_SMEM_FLOATS * sizeof(float)>>>(q, k, v, y);

    // 4) out = y @ w_out            [4096,2048]x[2048,2048]
    dim3 g3(C_ / 128, M_ / 128);
    sgemm128x128<<<g3, 256>>>(y, w_out, out, M_, C_, C_);
}

// round 5
// speedup vs baseline: 1.8594x; 1.8594x over previous
#include <cuda_runtime.h>
#include <math.h>
#include <stdint.h>

#define B_ 2
#define T_ 2048
#define C_ 2048
#define H_ 16
#define D_ 128
#define M_ (B_*T_)   // 4096

// ---------------- scratch (device globals; no allocation allowed) ----------------
__device__ float g_qkv[M_ * 3 * C_];           // [4096, 6144]
__device__ float g_q[B_ * H_ * T_ * D_];       // [B,H,T,D]
__device__ float g_k[B_ * H_ * T_ * D_];
__device__ float g_v[B_ * H_ * T_ * D_];
__device__ float g_y[M_ * C_];                 // attention out, [B,T,C]

// ============================ PTX helpers ========================================
__device__ __forceinline__ uint32_t smem_u32(const void* p) {
    return (uint32_t)__cvta_generic_to_shared(p);
}
__device__ __forceinline__ uint32_t tf32b(float x) {   // fp32 -> tf32 bits, round-nearest
    uint32_t u;
    asm("cvt.rna.tf32.f32 %0, %1;" : "=r"(u) : "f"(x));
    return u;
}
__device__ __forceinline__ void cp_async16(uint32_t s, const void* g) {
    asm volatile("cp.async.cg.shared.global [%0], [%1], 16;" :: "r"(s), "l"(g));
}
#define CP_ASYNC_COMMIT() asm volatile("cp.async.commit_group;" ::: "memory")
#define CP_ASYNC_WAIT1()  asm volatile("cp.async.wait_group 1;" ::: "memory")
#define CP_ASYNC_WAIT0()  asm volatile("cp.async.wait_group 0;" ::: "memory")

__device__ __forceinline__ void mma_tf32(float* d, const uint32_t* a, const uint32_t* b) {
    asm volatile(
        "mma.sync.aligned.m16n8k8.row.col.f32.tf32.tf32.f32 "
        "{%0,%1,%2,%3}, {%4,%5,%6,%7}, {%8,%9}, {%0,%1,%2,%3};"
        : "+f"(d[0]), "+f"(d[1]), "+f"(d[2]), "+f"(d[3])
        : "r"(a[0]), "r"(a[1]), "r"(a[2]), "r"(a[3]), "r"(b[0]), "r"(b[1]));
}

// ============= tensor-core tf32 GEMM: C[M,N] = A[M,K] @ B[K,N] ===================
// 128x128 block tile, BK=32, 8 warps (4x2), warp tile 32x64 (2x8 m16n8k8 frags),
// double-buffered cp.async pipeline. fp32->tf32 rounding done in registers.
#define GBM 128
#define GBN 128
#define GBK 32
#define ASTR 36      // As[row][k], stride 36 floats (conflict-free a-frag LDS)
#define BSTR 132     // Bs[k][n],  stride 132 floats
#define ABUF (GBM*ASTR)      // 4608 floats
#define BBUF (GBK*BSTR)      // 4224 floats
#define G_SMEM_BYTES ((2*ABUF + 2*BBUF) * 4)   // 70656 B

__global__ __launch_bounds__(256, 2)
void gemm_mma_tf32(const float* __restrict__ A, const float* __restrict__ Bm,
                   float* __restrict__ Cm, int M, int N, int K) {
    extern __shared__ __align__(16) float sm[];
    float* Asm = sm;               // 2 buffers
    float* Bsm = sm + 2 * ABUF;

    const int tid = threadIdx.x;
    const int wid = tid >> 5, lane = tid & 31;
    const int g = lane >> 2, tg = lane & 3;
    const int warp_m = (wid >> 1) * 32;
    const int warp_n = (wid & 1) * 64;
    const int m0 = blockIdx.y * GBM;
    const int n0 = blockIdx.x * GBN;

    const uint32_t aS = smem_u32(Asm);
    const uint32_t bS = smem_u32(Bsm);

    float acc[2][8][4];
    #pragma unroll
    for (int i = 0; i < 2; i++)
        #pragma unroll
        for (int j = 0; j < 8; j++)
            #pragma unroll
            for (int q = 0; q < 4; q++) acc[i][j][q] = 0.f;

    const int ntiles = K / GBK;

    // ---- tile loader (A: 128x32, B: 32x128) ----
    auto load_tile = [&](int kt, int buf) {
        const int kbase = kt * GBK;
        const uint32_t aDst = aS + buf * ABUF * 4;
        const uint32_t bDst = bS + buf * BBUF * 4;
        #pragma unroll
        for (int u = 0; u < 4; u++) {           // A: 1024 16B chunks
            const int e = u * 256 + tid;
            const int row = e >> 3, c4 = e & 7;
            cp_async16(aDst + (row * ASTR + c4 * 4) * 4,
                       A + (size_t)(m0 + row) * K + kbase + c4 * 4);
        }
        #pragma unroll
        for (int u = 0; u < 4; u++) {           // B: 1024 16B chunks
            const int e = u * 256 + tid;
            const int row = e >> 5, c4 = e & 31;
            cp_async16(bDst + (row * BSTR + c4 * 4) * 4,
                       Bm + (size_t)(kbase + row) * N + n0 + c4 * 4);
        }
        CP_ASYNC_COMMIT();
    };

    load_tile(0, 0);

    for (int kt = 0; kt < ntiles; kt++) {
        const int buf = kt & 1;
        if (kt + 1 < ntiles) {
            load_tile(kt + 1, buf ^ 1);
            CP_ASYNC_WAIT1();
        } else {
            CP_ASYNC_WAIT0();
        }
        __syncthreads();

        const float* As = Asm + buf * ABUF;
        const float* Bs = Bsm + buf * BBUF;

        #pragma unroll
        for (int kk = 0; kk < GBK; kk += 8) {
            uint32_t afr[2][4], bfr[8][2];
            #pragma unroll
            for (int mt = 0; mt < 2; mt++) {
                const int r = warp_m + mt * 16 + g;
                afr[mt][0] = tf32b(As[r * ASTR + kk + tg]);
                afr[mt][1] = tf32b(As[(r + 8) * ASTR + kk + tg]);
                afr[mt][2] = tf32b(As[r * ASTR + kk + tg + 4]);
                afr[mt][3] = tf32b(As[(r + 8) * ASTR + kk + tg + 4]);
            }
            #pragma unroll
            for (int nt = 0; nt < 8; nt++) {
                const int c = warp_n + nt * 8 + g;
                bfr[nt][0] = tf32b(Bs[(kk + tg) * BSTR + c]);
                bfr[nt][1] = tf32b(Bs[(kk + tg + 4) * BSTR + c]);
            }
            #pragma unroll
            for (int mt = 0; mt < 2; mt++)
                #pragma unroll
                for (int nt = 0; nt < 8; nt++)
                    mma_tf32(acc[mt][nt], afr[mt], bfr[nt]);
        }
        __syncthreads();
    }

    // ---- epilogue ----
    #pragma unroll
    for (int mt = 0; mt < 2; mt++) {
        const int r = m0 + warp_m + mt * 16 + g;
        #pragma unroll
        for (int nt = 0; nt < 8; nt++) {
            const int c = n0 + warp_n + nt * 8 + tg * 2;
            *(float2*)(Cm + (size_t)r * N + c)       = make_float2(acc[mt][nt][0], acc[mt][nt][1]);
            *(float2*)(Cm + (size_t)(r + 8) * N + c) = make_float2(acc[mt][nt][2], acc[mt][nt][3]);
        }
    }
}

// ---------------- RoPE + split/transpose + fold 1/sqrt(D) into Q -----------------
__global__ void rope_split_kernel(const float* __restrict__ qkv,
                                  float* __restrict__ Qo, float* __restrict__ Ko,
                                  float* __restrict__ Vo) {
    int idx = blockIdx.x * blockDim.x + threadIdx.x;
    if (idx >= B_ * T_ * H_ * 64) return;
    const int i = idx & 63;
    const int h = (idx >> 6) & 15;
    const int t = (idx >> 10) & (T_ - 1);
    const int b = idx >> 21;

    const float* row = qkv + (size_t)(b * T_ + t) * (3 * C_);
    const float inv = powf(10000.f, -(float)i / 64.f);
    const float f = (float)t * inv;
    float s, c;
    sincosf(f, &s, &c);

    const float q0 = row[h * D_ + i],            q1 = row[h * D_ + i + 64];
    const float k0 = row[C_ + h * D_ + i],       k1 = row[C_ + h * D_ + i + 64];
    const float v0 = row[2 * C_ + h * D_ + i],   v1 = row[2 * C_ + h * D_ + i + 64];

    const size_t o = ((size_t)(b * H_ + h) * T_ + t) * D_ + i;
    const float sc = 0.08838834764831845f;   // 1/sqrt(128)
    Qo[o]      = (q0 * c - q1 * s) * sc;
    Qo[o + 64] = (q1 * c + q0 * s) * sc;
    Ko[o]      = k0 * c - k1 * s;
    Ko[o + 64] = k1 * c + k0 * s;
    Vo[o]      = v0;
    Vo[o + 64] = v1;
}

// ---------------- fp32 flash attention, causal, BQ=BK=128, D=128 ----------------
#define FL_SMEM_FLOATS (2 * 128 * 132 + 128 * 128)   // Qt + (Kt|Ps) + Vs = 50176

__global__ __launch_bounds__(256, 1)
void flash_attn(const float* __restrict__ Qg, const float* __restrict__ Kg,
                const float* __restrict__ Vg, float* __restrict__ Yg) {
    extern __shared__ __align__(16) float sm[];
    float* Qt   = sm;                  // Qt[d*132 + r]  (transposed)
    float* KtPs = sm + 128 * 132;      // Kt[d*132 + c]  then  Ps[r*132 + c]
    float* Vs   = sm + 2 * 128 * 132;  // Vs[c*128 + d]  (natural)

    const int tid = threadIdx.x;
    const int tn = tid & 15;
    const int tm = tid >> 4;
    const int qi = gridDim.x - 1 - blockIdx.x;   // heavy blocks first
    const int h = blockIdx.y;
    const int b = blockIdx.z;
    const size_t bh = (size_t)(b * H_ + h);
    const float* Qb = Qg + bh * T_ * D_ + (size_t)qi * 128 * D_;
    const float* Kb = Kg + bh * T_ * D_;
    const float* Vb = Vg + bh * T_ * D_;

    const int lrow = tid >> 1;
    const int c4b = (tid & 1) * 16;

    #pragma unroll
    for (int u = 0; u < 16; u++) {
        const int c4 = c4b + u;
        float4 v = *(const float4*)(Qb + lrow * D_ + c4 * 4);
        Qt[(c4 * 4 + 0) * 132 + lrow] = v.x;
        Qt[(c4 * 4 + 1) * 132 + lrow] = v.y;
        Qt[(c4 * 4 + 2) * 132 + lrow] = v.z;
        Qt[(c4 * 4 + 3) * 132 + lrow] = v.w;
    }

    float o[8][8];
    float m_i[8], l_i[8];
    #pragma unroll
    for (int i = 0; i < 8; i++) {
        m_i[i] = -INFINITY;
        l_i[i] = 0.f;
        #pragma unroll
        for (int j = 0; j < 8; j++) o[i][j] = 0.f;
    }

    for (int kt = 0; kt <= qi; kt++) {
        const float* Kt_g = Kb + (size_t)kt * 128 * D_;
        const float* Vt_g = Vb + (size_t)kt * 128 * D_;

        #pragma unroll
        for (int u = 0; u < 16; u++) {
            const int c4 = c4b + u;
            float4 v = *(const float4*)(Kt_g + lrow * D_ + c4 * 4);
            KtPs[(c4 * 4 + 0) * 132 + lrow] = v.x;
            KtPs[(c4 * 4 + 1) * 132 + lrow] = v.y;
            KtPs[(c4 * 4 + 2) * 132 + lrow] = v.z;
            KtPs[(c4 * 4 + 3) * 132 + lrow] = v.w;
        }
        #pragma unroll
        for (int u = 0; u < 16; u++) {
            const int e = u * 256 + tid;
            const int r = e >> 5, c4 = e & 31;
            *(float4*)&Vs[r * 128 + c4 * 4] = *(const float4*)(Vt_g + r * 128 + c4 * 4);
        }
        __syncthreads();

        float s[8][8];
        #pragma unroll
        for (int i = 0; i < 8; i++)
            #pragma unroll
            for (int j = 0; j < 8; j++) s[i][j] = 0.f;

        #pragma unroll 2
        for (int d = 0; d < 128; d++) {
            float a[8], bb[8];
            *(float4*)&a[0]  = *(const float4*)&Qt[d * 132 + tm * 8];
            *(float4*)&a[4]  = *(const float4*)&Qt[d * 132 + tm * 8 + 4];
            *(float4*)&bb[0] = *(const float4*)&KtPs[d * 132 + tn * 8];
            *(float4*)&bb[4] = *(const float4*)&KtPs[d * 132 + tn * 8 + 4];
            #pragma unroll
            for (int i = 0; i < 8; i++)
                #pragma unroll
                for (int j = 0; j < 8; j++)
                    s[i][j] = fmaf(a[i], bb[j], s[i][j]);
        }

        if (kt == qi) {
            #pragma unroll
            for (int i = 0; i < 8; i++)
                #pragma unroll
                for (int j = 0; j < 8; j++)
                    if (tn * 8 + j > tm * 8 + i) s[i][j] = -INFINITY;
        }

        #pragma unroll
        for (int i = 0; i < 8; i++) {
            float mx = s[i][0];
            #pragma unroll
            for (int j = 1; j < 8; j++) mx = fmaxf(mx, s[i][j]);
            #pragma unroll
            for (int off = 8; off >= 1; off >>= 1)
                mx = fmaxf(mx, __shfl_xor_sync(0xffffffffu, mx, off));
            const float mnew = fmaxf(m_i[i], mx);
            const float alpha = __expf(m_i[i] - mnew);
            m_i[i] = mnew;
            float rs = 0.f;
            #pragma unroll
            for (int j = 0; j < 8; j++) {
                s[i][j] = __expf(s[i][j] - mnew);
                rs += s[i][j];
            }
            #pragma unroll
            for (int off = 8; off >= 1; off >>= 1)
                rs += __shfl_xor_sync(0xffffffffu, rs, off);
            l_i[i] = l_i[i] * alpha + rs;
            #pragma unroll
            for (int j = 0; j < 8; j++) o[i][j] *= alpha;
        }

        __syncthreads();
        #pragma unroll
        for (int i = 0; i < 8; i++) {
            float* pp = &KtPs[(tm * 8 + i) * 132 + tn * 8];
            *(float4*)pp       = make_float4(s[i][0], s[i][1], s[i][2], s[i][3]);
            *(float4*)(pp + 4) = make_float4(s[i][4], s[i][5], s[i][6], s[i][7]);
        }
        __syncthreads();

        #pragma unroll 2
        for (int c = 0; c < 128; c++) {
            float p[8], vv[8];
            #pragma unroll
            for (int i = 0; i < 8; i++) p[i] = KtPs[(tm * 8 + i) * 132 + c];
            *(float4*)&vv[0] = *(const float4*)&Vs[c * 128 + tn * 8];
            *(float4*)&vv[4] = *(const float4*)&Vs[c * 128 + tn * 8 + 4];
            #pragma unroll
            for (int i = 0; i < 8; i++)
                #pragma unroll
                for (int j = 0; j < 8; j++)
                    o[i][j] = fmaf(p[i], vv[j], o[i][j]);
        }
        __syncthreads();
    }

    #pragma unroll
    for (int i = 0; i < 8; i++) {
        const float inv = 1.0f / l_i[i];
        const int grow = qi * 128 + tm * 8 + i;
        float* yp = Yg + ((size_t)b * T_ + grow) * C_ + h * D_ + tn * 8;
        *(float4*)yp       = make_float4(o[i][0] * inv, o[i][1] * inv, o[i][2] * inv, o[i][3] * inv);
        *(float4*)(yp + 4) = make_float4(o[i][4] * inv, o[i][5] * inv, o[i][6] * inv, o[i][7] * inv);
    }
}

// ------------------------------------ launch -------------------------------------
extern "C" void kernel_launch(void* const* d_in, const int* in_sizes, int n_in,
                              void* d_out, int out_size) {
    const float* x     = (const float*)d_in[0];
    const float* w_qkv = (const float*)d_in[1];
    const float* w_out = (const float*)d_in[2];
    float* out = (float*)d_out;

    float *qkv, *q, *k, *v, *y;
    cudaGetSymbolAddress((void**)&qkv, g_qkv);
    cudaGetSymbolAddress((void**)&q, g_q);
    cudaGetSymbolAddress((void**)&k, g_k);
    cudaGetSymbolAddress((void**)&v, g_v);
    cudaGetSymbolAddress((void**)&y, g_y);

    cudaFuncSetAttribute(flash_attn, cudaFuncAttributeMaxDynamicSharedMemorySize,
                         FL_SMEM_FLOATS * (int)sizeof(float));
    cudaFuncSetAttribute(gemm_mma_tf32, cudaFuncAttributeMaxDynamicSharedMemorySize,
                         G_SMEM_BYTES);

    // 1) qkv = x @ w_qkv   (tensor core tf32 via mma.sync)
    dim3 g1(3 * C_ / GBN, M_ / GBM);
    gemm_mma_tf32<<<g1, 256, G_SMEM_BYTES>>>(x, w_qkv, qkv, M_, 3 * C_, C_);

    // 2) rope + split into Q,K,V [B,H,T,D]
    const int nrope = B_ * T_ * H_ * 64;
    rope_split_kernel<<<nrope / 256, 256>>>(qkv, q, k, v);

    // 3) causal flash attention -> y [B,T,C]
    dim3 g2(T_ / 128, H_, B_);
    flash_attn<<<g2, 256, FL_SMEM_FLOATS * sizeof(float)>>>(q, k, v, y);

    // 4) out = y @ w_out   (tensor core tf32 via mma.sync)
    dim3 g3(C_ / GBN, M_ / GBM);
    gemm_mma_tf32<<<g3, 256, G_SMEM_BYTES>>>(y, w_out, out, M_, C_, C_);
}

// round 7
// speedup vs baseline: 1.9267x; 1.0362x over previous
#include <cuda_runtime.h>
#include <math.h>
#include <stdint.h>

#define B_ 2
#define T_ 2048
#define C_ 2048
#define H_ 16
#define D_ 128
#define M_ (B_*T_)   // 4096

// ---------------- scratch (device globals; no allocation allowed) ----------------
__device__ float g_qkv[M_ * 3 * C_];           // [4096, 6144]
__device__ float g_q[B_ * H_ * T_ * D_];       // [B,H,T,D] (tf32-rounded)
__device__ float g_k[B_ * H_ * T_ * D_];
__device__ float g_v[B_ * H_ * T_ * D_];
__device__ float g_y[M_ * C_];                 // attention out (tf32-rounded)
__device__ float g_xt[M_ * C_];                // tf32-rounded x
__device__ float g_wq[3 * C_ * C_];            // tf32-rounded w_qkv
__device__ float g_wo[C_ * C_];                // tf32-rounded w_out

// ============================ PTX helpers ========================================
__device__ __forceinline__ uint32_t smem_u32(const void* p) {
    return (uint32_t)__cvta_generic_to_shared(p);
}
__device__ __forceinline__ uint32_t tf32b(float x) {   // fp32 -> tf32 bits, rna
    uint32_t u;
    asm("cvt.rna.tf32.f32 %0, %1;" : "=r"(u) : "f"(x));
    return u;
}
__device__ __forceinline__ void cp_async16(uint32_t s, const void* g) {
    asm volatile("cp.async.cg.shared.global [%0], [%1], 16;" :: "r"(s), "l"(g));
}
#define CP_ASYNC_COMMIT() asm volatile("cp.async.commit_group;" ::: "memory")
#define CP_ASYNC_WAIT1()  asm volatile("cp.async.wait_group 1;" ::: "memory")
#define CP_ASYNC_WAIT0()  asm volatile("cp.async.wait_group 0;" ::: "memory")

__device__ __forceinline__ void mma_tf32(float* d, const uint32_t* a, const uint32_t* b) {
    asm volatile(
        "mma.sync.aligned.m16n8k8.row.col.f32.tf32.tf32.f32 "
        "{%0,%1,%2,%3}, {%4,%5,%6,%7}, {%8,%9}, {%0,%1,%2,%3};"
        : "+f"(d[0]), "+f"(d[1]), "+f"(d[2]), "+f"(d[3])
        : "r"(a[0]), "r"(a[1]), "r"(a[2]), "r"(a[3]), "r"(b[0]), "r"(b[1]));
}

// ============= tensor-core tf32 GEMM: C[M,N] = A[M,K] @ B[K,N] ===================
// inputs pre-rounded to tf32; inner loop loads raw bits (no cvt).
#define GBM 128
#define GBN 128
#define GBK 32
#define ASTR 36
#define BSTR 132
#define ABUF (GBM*ASTR)
#define BBUF (GBK*BSTR)
#define G_SMEM_BYTES ((2*ABUF + 2*BBUF) * 4)

__global__ __launch_bounds__(256, 2)
void gemm_mma_tf32(const float* __restrict__ A, const float* __restrict__ Bm,
                   float* __restrict__ Cm, int M, int N, int K) {
    extern __shared__ __align__(16) float sm[];
    float* Asm = sm;
    float* Bsm = sm + 2 * ABUF;

    const int tid = threadIdx.x;
    const int wid = tid >> 5, lane = tid & 31;
    const int g = lane >> 2, tg = lane & 3;
    const int warp_m = (wid >> 1) * 32;
    const int warp_n = (wid & 1) * 64;
    const int m0 = blockIdx.y * GBM;
    const int n0 = blockIdx.x * GBN;

    const uint32_t aS = smem_u32(Asm);
    const uint32_t bS = smem_u32(Bsm);

    float acc[2][8][4];
    #pragma unroll
    for (int i = 0; i < 2; i++)
        #pragma unroll
        for (int j = 0; j < 8; j++)
            #pragma unroll
            for (int q = 0; q < 4; q++) acc[i][j][q] = 0.f;

    const int ntiles = K / GBK;

    auto load_tile = [&](int kt, int buf) {
        const int kbase = kt * GBK;
        const uint32_t aDst = aS + buf * ABUF * 4;
        const uint32_t bDst = bS + buf * BBUF * 4;
        #pragma unroll
        for (int u = 0; u < 4; u++) {
            const int e = u * 256 + tid;
            const int row = e >> 3, c4 = e & 7;
            cp_async16(aDst + (row * ASTR + c4 * 4) * 4,
                       A + (size_t)(m0 + row) * K + kbase + c4 * 4);
        }
        #pragma unroll
        for (int u = 0; u < 4; u++) {
            const int e = u * 256 + tid;
            const int row = e >> 5, c4 = e & 31;
            cp_async16(bDst + (row * BSTR + c4 * 4) * 4,
                       Bm + (size_t)(kbase + row) * N + n0 + c4 * 4);
        }
        CP_ASYNC_COMMIT();
    };

    load_tile(0, 0);

    for (int kt = 0; kt < ntiles; kt++) {
        const int buf = kt & 1;
        if (kt + 1 < ntiles) {
            load_tile(kt + 1, buf ^ 1);
            CP_ASYNC_WAIT1();
        } else {
            CP_ASYNC_WAIT0();
        }
        __syncthreads();

        const float* As = Asm + buf * ABUF;
        const float* Bs = Bsm + buf * BBUF;

        #pragma unroll
        for (int kk = 0; kk < GBK; kk += 8) {
            uint32_t afr[2][4], bfr[8][2];
            #pragma unroll
            for (int mt = 0; mt < 2; mt++) {
                const int r = warp_m + mt * 16 + g;
                afr[mt][0] = __float_as_uint(As[r * ASTR + kk + tg]);
                afr[mt][1] = __float_as_uint(As[(r + 8) * ASTR + kk + tg]);
                afr[mt][2] = __float_as_uint(As[r * ASTR + kk + tg + 4]);
                afr[mt][3] = __float_as_uint(As[(r + 8) * ASTR + kk + tg + 4]);
            }
            #pragma unroll
            for (int nt = 0; nt < 8; nt++) {
                const int c = warp_n + nt * 8 + g;
                bfr[nt][0] = __float_as_uint(Bs[(kk + tg) * BSTR + c]);
                bfr[nt][1] = __float_as_uint(Bs[(kk + tg + 4) * BSTR + c]);
            }
            #pragma unroll
            for (int mt = 0; mt < 2; mt++)
                #pragma unroll
                for (int nt = 0; nt < 8; nt++)
                    mma_tf32(acc[mt][nt], afr[mt], bfr[nt]);
        }
        __syncthreads();
    }

    #pragma unroll
    for (int mt = 0; mt < 2; mt++) {
        const int r = m0 + warp_m + mt * 16 + g;
        #pragma unroll
        for (int nt = 0; nt < 8; nt++) {
            const int c = n0 + warp_n + nt * 8 + tg * 2;
            *(float2*)(Cm + (size_t)r * N + c)       = make_float2(acc[mt][nt][0], acc[mt][nt][1]);
            *(float2*)(Cm + (size_t)(r + 8) * N + c) = make_float2(acc[mt][nt][2], acc[mt][nt][3]);
        }
    }
}

// ---------------- staging: tf32 round-copy --------------------------------------
__global__ void round_copy_tf32(const float* __restrict__ in, float* __restrict__ out) {
    const int i = (blockIdx.x * blockDim.x + threadIdx.x) * 4;
    float4 v = *(const float4*)(in + i);
    v.x = __uint_as_float(tf32b(v.x));
    v.y = __uint_as_float(tf32b(v.y));
    v.z = __uint_as_float(tf32b(v.z));
    v.w = __uint_as_float(tf32b(v.w));
    *(float4*)(out + i) = v;
}

// ---------------- RoPE + split + fold 1/sqrt(D) into Q, tf32-round outputs ------
__global__ void rope_split_kernel(const float* __restrict__ qkv,
                                  float* __restrict__ Qo, float* __restrict__ Ko,
                                  float* __restrict__ Vo) {
    int idx = blockIdx.x * blockDim.x + threadIdx.x;
    if (idx >= B_ * T_ * H_ * 64) return;
    const int i = idx & 63;
    const int h = (idx >> 6) & 15;
    const int t = (idx >> 10) & (T_ - 1);
    const int b = idx >> 21;

    const float* row = qkv + (size_t)(b * T_ + t) * (3 * C_);
    const float inv = powf(10000.f, -(float)i / 64.f);
    const float f = (float)t * inv;
    float s, c;
    sincosf(f, &s, &c);

    const float q0 = row[h * D_ + i],            q1 = row[h * D_ + i + 64];
    const float k0 = row[C_ + h * D_ + i],       k1 = row[C_ + h * D_ + i + 64];
    const float v0 = row[2 * C_ + h * D_ + i],   v1 = row[2 * C_ + h * D_ + i + 64];

    const size_t o = ((size_t)(b * H_ + h) * T_ + t) * D_ + i;
    const float sc = 0.08838834764831845f;   // 1/sqrt(128)
    Qo[o]      = __uint_as_float(tf32b((q0 * c - q1 * s) * sc));
    Qo[o + 64] = __uint_as_float(tf32b((q1 * c + q0 * s) * sc));
    Ko[o]      = __uint_as_float(tf32b(k0 * c - k1 * s));
    Ko[o + 64] = __uint_as_float(tf32b(k1 * c + k0 * s));
    Vo[o]      = __uint_as_float(tf32b(v0));
    Vo[o + 64] = __uint_as_float(tf32b(v1));
}

// ============ tensor-core flash attention, causal, BQ=BK=128, D=128 ==============
// 8 warps (4x2), warp tile 32x64 for S and O; P round-trips through K buffer.
#define QSTR 132
#define VSTR 136
#define FA_QOFF 0
#define FA_KOFF (128*QSTR)
#define FA_VOFF (2*128*QSTR)
#define FA_RMAX (2*128*QSTR + 128*VSTR)
#define FA_RSUM (FA_RMAX + 256)
#define FA_SMEM_FLOATS (FA_RSUM + 256)
#define FA_SMEM_BYTES (FA_SMEM_FLOATS * 4)   // 206848

__global__ __launch_bounds__(256, 1)
void flash_attn_tc(const float* __restrict__ Qg, const float* __restrict__ Kg,
                   const float* __restrict__ Vg, float* __restrict__ Yg) {
    extern __shared__ __align__(16) float sm[];
    float* Qs = sm + FA_QOFF;
    float* KPs = sm + FA_KOFF;     // K tile, later P tile
    float* Vs = sm + FA_VOFF;
    float* rmax = sm + FA_RMAX;    // [128][2]
    float* rsum = sm + FA_RSUM;

    const int tid = threadIdx.x;
    const int wid = tid >> 5, lane = tid & 31;
    const int g = lane >> 2, tg = lane & 3;
    const int wm = wid >> 1, wn = wid & 1;

    const int qi = gridDim.x - 1 - blockIdx.x;   // heavy blocks first
    const int h = blockIdx.y;
    const int b = blockIdx.z;
    const size_t bh = (size_t)(b * H_ + h);
    const float* Qb = Qg + bh * T_ * D_ + (size_t)qi * 128 * D_;
    const float* Kb = Kg + bh * T_ * D_;
    const float* Vb = Vg + bh * T_ * D_;

    // load Q tile (natural layout, stride 132)
    #pragma unroll
    for (int u = 0; u < 16; u++) {
        const int e = u * 256 + tid;
        const int r = e >> 5, c4 = e & 31;
        *(float4*)&Qs[r * QSTR + c4 * 4] = *(const float4*)(Qb + r * D_ + c4 * 4);
    }

    float o[2][8][4];
    float m_i[2][2], l_i[2][2];
    #pragma unroll
    for (int mt = 0; mt < 2; mt++) {
        m_i[mt][0] = -INFINITY; m_i[mt][1] = -INFINITY;
        l_i[mt][0] = 0.f;       l_i[mt][1] = 0.f;
        #pragma unroll
        for (int nt = 0; nt < 8; nt++)
            #pragma unroll
            for (int q = 0; q < 4; q++) o[mt][nt][q] = 0.f;
    }

    for (int kt = 0; kt <= qi; kt++) {
        const float* Kt_g = Kb + (size_t)kt * 128 * D_;
        const float* Vt_g = Vb + (size_t)kt * 128 * D_;
        #pragma unroll
        for (int u = 0; u < 16; u++) {
            const int e = u * 256 + tid;
            const int r = e >> 5, c4 = e & 31;
            *(float4*)&KPs[r * QSTR + c4 * 4] = *(const float4*)(Kt_g + r * D_ + c4 * 4);
        }
        #pragma unroll
        for (int u = 0; u < 16; u++) {
            const int e = u * 256 + tid;
            const int r = e >> 5, c4 = e & 31;
            *(float4*)&Vs[r * VSTR + c4 * 4] = *(const float4*)(Vt_g + r * D_ + c4 * 4);
        }
        __syncthreads();

        // ---- S = Q @ K^T (warp tile 32x64) ----
        float s[2][8][4];
        #pragma unroll
        for (int mt = 0; mt < 2; mt++)
            #pragma unroll
            for (int nt = 0; nt < 8; nt++)
                #pragma unroll
                for (int q = 0; q < 4; q++) s[mt][nt][q] = 0.f;

        #pragma unroll
        for (int kk = 0; kk < 16; kk++) {
            const int d0 = kk * 8;
            uint32_t a[2][4];
            #pragma unroll
            for (int mt = 0; mt < 2; mt++) {
                const int r = wm * 32 + mt * 16 + g;
                a[mt][0] = __float_as_uint(Qs[r * QSTR + d0 + tg]);
                a[mt][1] = __float_as_uint(Qs[(r + 8) * QSTR + d0 + tg]);
                a[mt][2] = __float_as_uint(Qs[r * QSTR + d0 + tg + 4]);
                a[mt][3] = __float_as_uint(Qs[(r + 8) * QSTR + d0 + tg + 4]);
            }
            #pragma unroll
            for (int nt = 0; nt < 8; nt++) {
                const int c = wn * 64 + nt * 8 + g;
                uint32_t bf[2];
                bf[0] = __float_as_uint(KPs[c * QSTR + d0 + tg]);
                bf[1] = __float_as_uint(KPs[c * QSTR + d0 + tg + 4]);
                mma_tf32(s[0][nt], a[0], bf);
                mma_tf32(s[1][nt], a[1], bf);
            }
        }

        // ---- causal mask on diagonal tile ----
        if (kt == qi) {
            #pragma unroll
            for (int mt = 0; mt < 2; mt++) {
                const int r0 = wm * 32 + mt * 16 + g;
                #pragma unroll
                for (int nt = 0; nt < 8; nt++) {
                    const int c0 = wn * 64 + nt * 8 + 2 * tg;
                    if (c0 > r0)         s[mt][nt][0] = -INFINITY;
                    if (c0 + 1 > r0)     s[mt][nt][1] = -INFINITY;
                    if (c0 > r0 + 8)     s[mt][nt][2] = -INFINITY;
                    if (c0 + 1 > r0 + 8) s[mt][nt][3] = -INFINITY;
                }
            }
        }

        // ---- row max: local -> tg-shfl -> smem exchange across warp pair ----
        float ml[2][2];
        #pragma unroll
        for (int mt = 0; mt < 2; mt++) {
            ml[mt][0] = -INFINITY; ml[mt][1] = -INFINITY;
            #pragma unroll
            for (int nt = 0; nt < 8; nt++) {
                ml[mt][0] = fmaxf(ml[mt][0], fmaxf(s[mt][nt][0], s[mt][nt][1]));
                ml[mt][1] = fmaxf(ml[mt][1], fmaxf(s[mt][nt][2], s[mt][nt][3]));
            }
            #pragma unroll
            for (int off = 1; off <= 2; off <<= 1) {
                ml[mt][0] = fmaxf(ml[mt][0], __shfl_xor_sync(0xffffffffu, ml[mt][0], off));
                ml[mt][1] = fmaxf(ml[mt][1], __shfl_xor_sync(0xffffffffu, ml[mt][1], off));
            }
        }
        if (tg == 0) {
            #pragma unroll
            for (int mt = 0; mt < 2; mt++) {
                const int r0 = wm * 32 + mt * 16 + g;
                rmax[r0 * 2 + wn] = ml[mt][0];
                rmax[(r0 + 8) * 2 + wn] = ml[mt][1];
            }
        }
        __syncthreads();

        // ---- combine max, exp, local sums, store P ----
        float alpha[2][2], sl[2][2];
        #pragma unroll
        for (int mt = 0; mt < 2; mt++) {
            #pragma unroll
            for (int hh = 0; hh < 2; hh++) {
                const int r = wm * 32 + mt * 16 + g + hh * 8;
                const float gm = fmaxf(rmax[r * 2], rmax[r * 2 + 1]);
                const float mnew = fmaxf(m_i[mt][hh], gm);
                alpha[mt][hh] = __expf(m_i[mt][hh] - mnew);
                m_i[mt][hh] = mnew;
                sl[mt][hh] = 0.f;
            }
        }
        #pragma unroll
        for (int mt = 0; mt < 2; mt++) {
            const int r0 = wm * 32 + mt * 16 + g;
            #pragma unroll
            for (int nt = 0; nt < 8; nt++) {
                const int c0 = wn * 64 + nt * 8 + 2 * tg;
                float e0 = __expf(s[mt][nt][0] - m_i[mt][0]);
                float e1 = __expf(s[mt][nt][1] - m_i[mt][0]);
                float e2 = __expf(s[mt][nt][2] - m_i[mt][1]);
                float e3 = __expf(s[mt][nt][3] - m_i[mt][1]);
                sl[mt][0] += e0 + e1;
                sl[mt][1] += e2 + e3;
                *(float2*)&KPs[r0 * QSTR + c0] =
                    make_float2(__uint_as_float(tf32b(e0)), __uint_as_float(tf32b(e1)));
                *(float2*)&KPs[(r0 + 8) * QSTR + c0] =
                    make_float2(__uint_as_float(tf32b(e2)), __uint_as_float(tf32b(e3)));
            }
            #pragma unroll
            for (int off = 1; off <= 2; off <<= 1) {
                sl[mt][0] += __shfl_xor_sync(0xffffffffu, sl[mt][0], off);
                sl[mt][1] += __shfl_xor_sync(0xffffffffu, sl[mt][1], off);
            }
        }
        if (tg == 0) {
            #pragma unroll
            for (int mt = 0; mt < 2; mt++) {
                const int r0 = wm * 32 + mt * 16 + g;
                rsum[r0 * 2 + wn] = sl[mt][0];
                rsum[(r0 + 8) * 2 + wn] = sl[mt][1];
            }
        }
        __syncthreads();

        // ---- l update + rescale O ----
        #pragma unroll
        for (int mt = 0; mt < 2; mt++) {
            #pragma unroll
            for (int hh = 0; hh < 2; hh++) {
                const int r = wm * 32 + mt * 16 + g + hh * 8;
                l_i[mt][hh] = l_i[mt][hh] * alpha[mt][hh] + rsum[r * 2] + rsum[r * 2 + 1];
            }
            #pragma unroll
            for (int nt = 0; nt < 8; nt++) {
                o[mt][nt][0] *= alpha[mt][0];
                o[mt][nt][1] *= alpha[mt][0];
                o[mt][nt][2] *= alpha[mt][1];
                o[mt][nt][3] *= alpha[mt][1];
            }
        }

        // ---- O += P @ V (warp tile 32x64 over D) ----
        #pragma unroll
        for (int kk = 0; kk < 16; kk++) {
            const int k0 = kk * 8;
            uint32_t a[2][4];
            #pragma unroll
            for (int mt = 0; mt < 2; mt++) {
                const int r = wm * 32 + mt * 16 + g;
                a[mt][0] = __float_as_uint(KPs[r * QSTR + k0 + tg]);
                a[mt][1] = __float_as_uint(KPs[(r + 8) * QSTR + k0 + tg]);
                a[mt][2] = __float_as_uint(KPs[r * QSTR + k0 + tg + 4]);
                a[mt][3] = __float_as_uint(KPs[(r + 8) * QSTR + k0 + tg + 4]);
            }
            #pragma unroll
            for (int nt = 0; nt < 8; nt++) {
                const int c = wn * 64 + nt * 8 + g;
                uint32_t bf[2];
                bf[0] = __float_as_uint(Vs[(k0 + tg) * VSTR + c]);
                bf[1] = __float_as_uint(Vs[(k0 + tg + 4) * VSTR + c]);
                mma_tf32(o[0][nt], a[0], bf);
                mma_tf32(o[1][nt], a[1], bf);
            }
        }
        __syncthreads();
    }

    // ---- epilogue: normalize, round to tf32, write [B,T,C] ----
    #pragma unroll
    for (int mt = 0; mt < 2; mt++) {
        const int r0 = wm * 32 + mt * 16 + g;
        const float inv0 = 1.0f / l_i[mt][0];
        const float inv1 = 1.0f / l_i[mt][1];
        #pragma unroll
        for (int nt = 0; nt < 8; nt++) {
            const int c0 = h * D_ + wn * 64 + nt * 8 + 2 * tg;
            const int gr0 = qi * 128 + r0;
            float* y0 = Yg + ((size_t)b * T_ + gr0) * C_ + c0;
            float* y1 = Yg + ((size_t)b * T_ + gr0 + 8) * C_ + c0;
            *(float2*)y0 = make_float2(__uint_as_float(tf32b(o[mt][nt][0] * inv0)),
                                       __uint_as_float(tf32b(o[mt][nt][1] * inv0)));
            *(float2*)y1 = make_float2(__uint_as_float(tf32b(o[mt][nt][2] * inv1)),
                                       __uint_as_float(tf32b(o[mt][nt][3] * inv1)));
        }
    }
}

// ------------------------------------ launch -------------------------------------
extern "C" void kernel_launch(void* const* d_in, const int* in_sizes, int n_in,
                              void* d_out, int out_size) {
    const float* x     = (const float*)d_in[0];
    const float* w_qkv = (const float*)d_in[1];
    const float* w_out = (const float*)d_in[2];
    float* out = (float*)d_out;

    float *qkv, *q, *k, *v, *y, *xt, *wq, *wo;
    cudaGetSymbolAddress((void**)&qkv, g_qkv);
    cudaGetSymbolAddress((void**)&q, g_q);
    cudaGetSymbolAddress((void**)&k, g_k);
    cudaGetSymbolAddress((void**)&v, g_v);
    cudaGetSymbolAddress((void**)&y, g_y);
    cudaGetSymbolAddress((void**)&xt, g_xt);
    cudaGetSymbolAddress((void**)&wq, g_wq);
    cudaGetSymbolAddress((void**)&wo, g_wo);

    cudaFuncSetAttribute(gemm_mma_tf32, cudaFuncAttributeMaxDynamicSharedMemorySize,
                         G_SMEM_BYTES);
    cudaFuncSetAttribute(flash_attn_tc, cudaFuncAttributeMaxDynamicSharedMemorySize,
                         FA_SMEM_BYTES);

    // staging: pre-round to tf32 (removes cvt from GEMM inner loops)
    round_copy_tf32<<<(M_ * C_) / 1024, 256>>>(x, xt);
    round_copy_tf32<<<(3 * C_ * C_) / 1024, 256>>>(w_qkv, wq);
    round_copy_tf32<<<(C_ * C_) / 1024, 256>>>(w_out, wo);

    // 1) qkv = x @ w_qkv
    dim3 g1(3 * C_ / GBN, M_ / GBM);
    gemm_mma_tf32<<<g1, 256, G_SMEM_BYTES>>>(xt, wq, qkv, M_, 3 * C_, C_);

    // 2) rope + split into Q,K,V [B,H,T,D] (tf32-rounded)
    const int nrope = B_ * T_ * H_ * 64;
    rope_split_kernel<<<nrope / 256, 256>>>(qkv, q, k, v);

    // 3) tensor-core causal flash attention -> y [B,T,C]
    dim3 g2(T_ / 128, H_, B_);
    flash_attn_tc<<<g2, 256, FA_SMEM_BYTES>>>(q, k, v, y);

    // 4) out = y @ w_out
    dim3 g3(C_ / GBN, M_ / GBM);
    gemm_mma_tf32<<<g3, 256, G_SMEM_BYTES>>>(y, wo, out, M_, C_, C_);
}

// round 8
// speedup vs baseline: 2.9506x; 1.5315x over previous
#include <cuda_runtime.h>
#include <math.h>
#include <stdint.h>

#define B_ 2
#define T_ 2048
#define C_ 2048
#define H_ 16
#define D_ 128
#define M_ (B_*T_)   // 4096

// ---------------- scratch (device globals; no allocation allowed) ----------------
__device__ float g_qkv[M_ * 3 * C_];           // [4096, 6144]
__device__ float g_q[B_ * H_ * T_ * D_];       // [B,H,T,D] (tf32-rounded)
__device__ float g_k[B_ * H_ * T_ * D_];
__device__ float g_v[B_ * H_ * T_ * D_];
__device__ float g_y[M_ * C_];                 // attention out (tf32-rounded)
__device__ float g_xt[M_ * C_];                // tf32-rounded x
__device__ float g_wq[3 * C_ * C_];            // tf32-rounded w_qkv
__device__ float g_wo[C_ * C_];                // tf32-rounded w_out

// ============================ PTX helpers ========================================
__device__ __forceinline__ uint32_t smem_u32(const void* p) {
    return (uint32_t)__cvta_generic_to_shared(p);
}
__device__ __forceinline__ uint32_t tf32b(float x) {   // fp32 -> tf32 bits, rna
    uint32_t u;
    asm("cvt.rna.tf32.f32 %0, %1;" : "=r"(u) : "f"(x));
    return u;
}
__device__ __forceinline__ void cp_async16(uint32_t s, const void* g) {
    asm volatile("cp.async.cg.shared.global [%0], [%1], 16;" :: "r"(s), "l"(g));
}
#define CP_ASYNC_COMMIT() asm volatile("cp.async.commit_group;" ::: "memory")
#define CP_ASYNC_WAIT1()  asm volatile("cp.async.wait_group 1;" ::: "memory")
#define CP_ASYNC_WAIT0()  asm volatile("cp.async.wait_group 0;" ::: "memory")

__device__ __forceinline__ void mma_tf32(float* d, const uint32_t* a, const uint32_t* b) {
    asm volatile(
        "mma.sync.aligned.m16n8k8.row.col.f32.tf32.tf32.f32 "
        "{%0,%1,%2,%3}, {%4,%5,%6,%7}, {%8,%9}, {%0,%1,%2,%3};"
        : "+f"(d[0]), "+f"(d[1]), "+f"(d[2]), "+f"(d[3])
        : "r"(a[0]), "r"(a[1]), "r"(a[2]), "r"(a[3]), "r"(b[0]), "r"(b[1]));
}

// ============= tensor-core tf32 GEMM: C[M,N] = A[M,K] @ B[K,N] ===================
#define GBM 128
#define GBN 128
#define GBK 32
#define ASTR 36
#define BSTR 132
#define ABUF (GBM*ASTR)
#define BBUF (GBK*BSTR)
#define G_SMEM_BYTES ((2*ABUF + 2*BBUF) * 4)

__global__ __launch_bounds__(256, 2)
void gemm_mma_tf32(const float* __restrict__ A, const float* __restrict__ Bm,
                   float* __restrict__ Cm, int M, int N, int K) {
    extern __shared__ __align__(16) float sm[];
    float* Asm = sm;
    float* Bsm = sm + 2 * ABUF;

    const int tid = threadIdx.x;
    const int wid = tid >> 5, lane = tid & 31;
    const int g = lane >> 2, tg = lane & 3;
    const int warp_m = (wid >> 1) * 32;
    const int warp_n = (wid & 1) * 64;
    const int m0 = blockIdx.y * GBM;
    const int n0 = blockIdx.x * GBN;

    const uint32_t aS = smem_u32(Asm);
    const uint32_t bS = smem_u32(Bsm);

    float acc[2][8][4];
    #pragma unroll
    for (int i = 0; i < 2; i++)
        #pragma unroll
        for (int j = 0; j < 8; j++)
            #pragma unroll
            for (int q = 0; q < 4; q++) acc[i][j][q] = 0.f;

    const int ntiles = K / GBK;

    auto load_tile = [&](int kt, int buf) {
        const int kbase = kt * GBK;
        const uint32_t aDst = aS + buf * ABUF * 4;
        const uint32_t bDst = bS + buf * BBUF * 4;
        #pragma unroll
        for (int u = 0; u < 4; u++) {
            const int e = u * 256 + tid;
            const int row = e >> 3, c4 = e & 7;
            cp_async16(aDst + (row * ASTR + c4 * 4) * 4,
                       A + (size_t)(m0 + row) * K + kbase + c4 * 4);
        }
        #pragma unroll
        for (int u = 0; u < 4; u++) {
            const int e = u * 256 + tid;
            const int row = e >> 5, c4 = e & 31;
            cp_async16(bDst + (row * BSTR + c4 * 4) * 4,
                       Bm + (size_t)(kbase + row) * N + n0 + c4 * 4);
        }
        CP_ASYNC_COMMIT();
    };

    load_tile(0, 0);

    for (int kt = 0; kt < ntiles; kt++) {
        const int buf = kt & 1;
        if (kt + 1 < ntiles) {
            load_tile(kt + 1, buf ^ 1);
            CP_ASYNC_WAIT1();
        } else {
            CP_ASYNC_WAIT0();
        }
        __syncthreads();

        const float* As = Asm + buf * ABUF;
        const float* Bs = Bsm + buf * BBUF;

        #pragma unroll
        for (int kk = 0; kk < GBK; kk += 8) {
            uint32_t afr[2][4], bfr[8][2];
            #pragma unroll
            for (int mt = 0; mt < 2; mt++) {
                const int r = warp_m + mt * 16 + g;
                afr[mt][0] = __float_as_uint(As[r * ASTR + kk + tg]);
                afr[mt][1] = __float_as_uint(As[(r + 8) * ASTR + kk + tg]);
                afr[mt][2] = __float_as_uint(As[r * ASTR + kk + tg + 4]);
                afr[mt][3] = __float_as_uint(As[(r + 8) * ASTR + kk + tg + 4]);
            }
            #pragma unroll
            for (int nt = 0; nt < 8; nt++) {
                const int c = warp_n + nt * 8 + g;
                bfr[nt][0] = __float_as_uint(Bs[(kk + tg) * BSTR + c]);
                bfr[nt][1] = __float_as_uint(Bs[(kk + tg + 4) * BSTR + c]);
            }
            #pragma unroll
            for (int mt = 0; mt < 2; mt++)
                #pragma unroll
                for (int nt = 0; nt < 8; nt++)
                    mma_tf32(acc[mt][nt], afr[mt], bfr[nt]);
        }
        __syncthreads();
    }

    #pragma unroll
    for (int mt = 0; mt < 2; mt++) {
        const int r = m0 + warp_m + mt * 16 + g;
        #pragma unroll
        for (int nt = 0; nt < 8; nt++) {
            const int c = n0 + warp_n + nt * 8 + tg * 2;
            *(float2*)(Cm + (size_t)r * N + c)       = make_float2(acc[mt][nt][0], acc[mt][nt][1]);
            *(float2*)(Cm + (size_t)(r + 8) * N + c) = make_float2(acc[mt][nt][2], acc[mt][nt][3]);
        }
    }
}

// ---------------- staging: tf32 round-copy --------------------------------------
__global__ void round_copy_tf32(const float* __restrict__ in, float* __restrict__ out) {
    const int i = (blockIdx.x * blockDim.x + threadIdx.x) * 4;
    float4 v = *(const float4*)(in + i);
    v.x = __uint_as_float(tf32b(v.x));
    v.y = __uint_as_float(tf32b(v.y));
    v.z = __uint_as_float(tf32b(v.z));
    v.w = __uint_as_float(tf32b(v.w));
    *(float4*)(out + i) = v;
}

// ---------------- RoPE + split + fold 1/sqrt(D) into Q, tf32-round outputs ------
__global__ void rope_split_kernel(const float* __restrict__ qkv,
                                  float* __restrict__ Qo, float* __restrict__ Ko,
                                  float* __restrict__ Vo) {
    int idx = blockIdx.x * blockDim.x + threadIdx.x;
    if (idx >= B_ * T_ * H_ * 64) return;
    const int i = idx & 63;
    const int h = (idx >> 6) & 15;
    const int t = (idx >> 10) & (T_ - 1);
    const int b = idx >> 21;

    const float* row = qkv + (size_t)(b * T_ + t) * (3 * C_);
    const float inv = powf(10000.f, -(float)i / 64.f);
    const float f = (float)t * inv;
    float s, c;
    sincosf(f, &s, &c);

    const float q0 = row[h * D_ + i],            q1 = row[h * D_ + i + 64];
    const float k0 = row[C_ + h * D_ + i],       k1 = row[C_ + h * D_ + i + 64];
    const float v0 = row[2 * C_ + h * D_ + i],   v1 = row[2 * C_ + h * D_ + i + 64];

    const size_t o = ((size_t)(b * H_ + h) * T_ + t) * D_ + i;
    const float sc = 0.08838834764831845f;   // 1/sqrt(128)
    Qo[o]      = __uint_as_float(tf32b((q0 * c - q1 * s) * sc));
    Qo[o + 64] = __uint_as_float(tf32b((q1 * c + q0 * s) * sc));
    Ko[o]      = __uint_as_float(tf32b(k0 * c - k1 * s));
    Ko[o + 64] = __uint_as_float(tf32b(k1 * c + k0 * s));
    Vo[o]      = __uint_as_float(tf32b(v0));
    Vo[o + 64] = __uint_as_float(tf32b(v1));
}

// ============ tensor-core flash attention v2: cp.async pipeline ==================
// BQ=128, BK=64, D=128. 8 warps; warp w owns rows w*16..w*16+15 (full 64 cols).
// Softmax fully warp-local (shfl over quad). P reuses current K buffer.
// One __syncthreads per k-chunk.
#define QSTR 132
#define KSTR 132
#define PSTR 66
#define VSTR 136
#define FA_QOFF 0
#define FA_K0 (128*QSTR)                 // 16896
#define FA_K1 (FA_K0 + 64*KSTR)          // +8448
#define FA_V0 (FA_K1 + 64*KSTR)
#define FA_V1 (FA_V0 + 64*VSTR)          // V buf = 8704
#define FA_SMEM_FLOATS (FA_V1 + 64*VSTR) // 51200
#define FA_SMEM_BYTES (FA_SMEM_FLOATS * 4)   // 204800

__global__ __launch_bounds__(256, 1)
void flash_attn_tc(const float* __restrict__ Qg, const float* __restrict__ Kg,
                   const float* __restrict__ Vg, float* __restrict__ Yg) {
    extern __shared__ __align__(16) float sm[];
    float* Qs = sm + FA_QOFF;

    const int tid = threadIdx.x;
    const int w = tid >> 5, lane = tid & 31;
    const int g = lane >> 2, tg = lane & 3;

    const int qi = gridDim.x - 1 - blockIdx.x;   // heavy blocks first
    const int h = blockIdx.y;
    const int b = blockIdx.z;
    const size_t bh = (size_t)(b * H_ + h);
    const float* Qp = Qg + bh * T_ * D_ + (size_t)qi * 128 * D_;
    const float* Kb = Kg + bh * T_ * D_;
    const float* Vb = Vg + bh * T_ * D_;

    const uint32_t smB = smem_u32(sm);
    const uint32_t kOff[2] = {smB + FA_K0 * 4, smB + FA_K1 * 4};
    const uint32_t vOff[2] = {smB + FA_V0 * 4, smB + FA_V1 * 4};

    // ---- issue Q tile loads (async) ----
    #pragma unroll
    for (int u = 0; u < 16; u++) {
        const int e = u * 256 + tid;
        const int r = e >> 5, c4 = e & 31;
        cp_async16(smB + (FA_QOFF + r * QSTR + c4 * 4) * 4, Qp + r * D_ + c4 * 4);
    }

    // ---- K/V chunk loader: 64 rows x 128 floats each ----
    auto load_kv = [&](int chunk, int buf) {
        const float* Kc = Kb + (size_t)chunk * 64 * D_;
        const float* Vc = Vb + (size_t)chunk * 64 * D_;
        #pragma unroll
        for (int u = 0; u < 8; u++) {
            const int e = u * 256 + tid;
            const int r = e >> 5, c4 = e & 31;
            cp_async16(kOff[buf] + (r * KSTR + c4 * 4) * 4, Kc + r * D_ + c4 * 4);
        }
        #pragma unroll
        for (int u = 0; u < 8; u++) {
            const int e = u * 256 + tid;
            const int r = e >> 5, c4 = e & 31;
            cp_async16(vOff[buf] + (r * VSTR + c4 * 4) * 4, Vc + r * D_ + c4 * 4);
        }
        CP_ASYNC_COMMIT();
    };

    load_kv(0, 0);   // Q rides in this first group too

    const int row0 = w * 16 + g;         // thread's first row (second is +8)
    const int nk = 2 * (qi + 1);

    float o[16][4];
    float m0 = -INFINITY, m1 = -INFINITY, l0 = 0.f, l1 = 0.f;
    #pragma unroll
    for (int nt = 0; nt < 16; nt++)
        #pragma unroll
        for (int q = 0; q < 4; q++) o[nt][q] = 0.f;

    for (int i = 0; i < nk; i++) {
        const int kb = i & 1;
        float* Ks = sm + (kb ? FA_K1 : FA_K0);
        float* Ps = Ks;                            // P reuses current K buffer
        float* Vs = sm + (kb ? FA_V1 : FA_V0);

        CP_ASYNC_WAIT0();
        __syncthreads();

        // ---- S = Q @ K^T : 16x64 per warp ----
        float s[8][4];
        #pragma unroll
        for (int nt = 0; nt < 8; nt++)
            #pragma unroll
            for (int q = 0; q < 4; q++) s[nt][q] = 0.f;

        #pragma unroll
        for (int kk = 0; kk < 16; kk++) {
            const int d0 = kk * 8;
            uint32_t a[4];
            a[0] = __float_as_uint(Qs[row0 * QSTR + d0 + tg]);
            a[1] = __float_as_uint(Qs[(row0 + 8) * QSTR + d0 + tg]);
            a[2] = __float_as_uint(Qs[row0 * QSTR + d0 + tg + 4]);
            a[3] = __float_as_uint(Qs[(row0 + 8) * QSTR + d0 + tg + 4]);
            #pragma unroll
            for (int nt = 0; nt < 8; nt++) {
                const int c = nt * 8 + g;
                uint32_t bf[2];
                bf[0] = __float_as_uint(Ks[c * KSTR + d0 + tg]);
                bf[1] = __float_as_uint(Ks[c * KSTR + d0 + tg + 4]);
                mma_tf32(s[nt], a, bf);
            }
        }

        // ---- causal mask (only the last two chunks can cross the diagonal) ----
        if (i >= 2 * qi) {
            const int rg0 = qi * 128 + row0;
            const int cb = i * 64;
            #pragma unroll
            for (int nt = 0; nt < 8; nt++) {
                const int c0 = cb + nt * 8 + 2 * tg;
                if (c0 > rg0)         s[nt][0] = -INFINITY;
                if (c0 + 1 > rg0)     s[nt][1] = -INFINITY;
                if (c0 > rg0 + 8)     s[nt][2] = -INFINITY;
                if (c0 + 1 > rg0 + 8) s[nt][3] = -INFINITY;
            }
        }

        // ---- warp-local online softmax (rows split over quad lanes tg) ----
        float ml0 = -INFINITY, ml1 = -INFINITY;
        #pragma unroll
        for (int nt = 0; nt < 8; nt++) {
            ml0 = fmaxf(ml0, fmaxf(s[nt][0], s[nt][1]));
            ml1 = fmaxf(ml1, fmaxf(s[nt][2], s[nt][3]));
        }
        #pragma unroll
        for (int off = 1; off <= 2; off <<= 1) {
            ml0 = fmaxf(ml0, __shfl_xor_sync(0xffffffffu, ml0, off));
            ml1 = fmaxf(ml1, __shfl_xor_sync(0xffffffffu, ml1, off));
        }
        const float mn0 = fmaxf(m0, ml0), mn1 = fmaxf(m1, ml1);
        const float al0 = __expf(m0 - mn0), al1 = __expf(m1 - mn1);
        m0 = mn0; m1 = mn1;

        float sl0 = 0.f, sl1 = 0.f;
        #pragma unroll
        for (int nt = 0; nt < 8; nt++) {
            const int c0 = nt * 8 + 2 * tg;
            float e0 = __expf(s[nt][0] - m0);
            float e1 = __expf(s[nt][1] - m0);
            float e2 = __expf(s[nt][2] - m1);
            float e3 = __expf(s[nt][3] - m1);
            sl0 += e0 + e1;
            sl1 += e2 + e3;
            *(float2*)&Ps[row0 * PSTR + c0] =
                make_float2(__uint_as_float(tf32b(e0)), __uint_as_float(tf32b(e1)));
            *(float2*)&Ps[(row0 + 8) * PSTR + c0] =
                make_float2(__uint_as_float(tf32b(e2)), __uint_as_float(tf32b(e3)));
        }
        #pragma unroll
        for (int off = 1; off <= 2; off <<= 1) {
            sl0 += __shfl_xor_sync(0xffffffffu, sl0, off);
            sl1 += __shfl_xor_sync(0xffffffffu, sl1, off);
        }
        l0 = l0 * al0 + sl0;
        l1 = l1 * al1 + sl1;

        // ---- prefetch next chunk (targets the other buffers) ----
        if (i + 1 < nk) load_kv(i + 1, kb ^ 1);

        // ---- rescale O ----
        #pragma unroll
        for (int nt = 0; nt < 16; nt++) {
            o[nt][0] *= al0; o[nt][1] *= al0;
            o[nt][2] *= al1; o[nt][3] *= al1;
        }

        // ---- O += P @ V : 16x128 per warp over k=64 ----
        #pragma unroll
        for (int kk = 0; kk < 8; kk++) {
            const int k0 = kk * 8;
            uint32_t a[4];
            a[0] = __float_as_uint(Ps[row0 * PSTR + k0 + tg]);
            a[1] = __float_as_uint(Ps[(row0 + 8) * PSTR + k0 + tg]);
            a[2] = __float_as_uint(Ps[row0 * PSTR + k0 + tg + 4]);
            a[3] = __float_as_uint(Ps[(row0 + 8) * PSTR + k0 + tg + 4]);
            #pragma unroll
            for (int nt = 0; nt < 16; nt++) {
                const int c = nt * 8 + g;
                uint32_t bf[2];
                bf[0] = __float_as_uint(Vs[(k0 + tg) * VSTR + c]);
                bf[1] = __float_as_uint(Vs[(k0 + tg + 4) * VSTR + c]);
                mma_tf32(o[nt], a, bf);
            }
        }
        // next iteration's top-of-loop barrier protects the buffers
    }

    // ---- epilogue: normalize, tf32-round, write [B,T,C] ----
    const float inv0 = 1.0f / l0, inv1 = 1.0f / l1;
    const int gr0 = qi * 128 + row0;
    #pragma unroll
    for (int nt = 0; nt < 16; nt++) {
        const int c0 = h * D_ + nt * 8 + 2 * tg;
        float* y0 = Yg + ((size_t)b * T_ + gr0) * C_ + c0;
        float* y1 = Yg + ((size_t)b * T_ + gr0 + 8) * C_ + c0;
        *(float2*)y0 = make_float2(__uint_as_float(tf32b(o[nt][0] * inv0)),
                                   __uint_as_float(tf32b(o[nt][1] * inv0)));
        *(float2*)y1 = make_float2(__uint_as_float(tf32b(o[nt][2] * inv1)),
                                   __uint_as_float(tf32b(o[nt][3] * inv1)));
    }
}

// ------------------------------------ launch -------------------------------------
extern "C" void kernel_launch(void* const* d_in, const int* in_sizes, int n_in,
                              void* d_out, int out_size) {
    const float* x     = (const float*)d_in[0];
    const float* w_qkv = (const float*)d_in[1];
    const float* w_out = (const float*)d_in[2];
    float* out = (float*)d_out;

    float *qkv, *q, *k, *v, *y, *xt, *wq, *wo;
    cudaGetSymbolAddress((void**)&qkv, g_qkv);
    cudaGetSymbolAddress((void**)&q, g_q);
    cudaGetSymbolAddress((void**)&k, g_k);
    cudaGetSymbolAddress((void**)&v, g_v);
    cudaGetSymbolAddress((void**)&y, g_y);
    cudaGetSymbolAddress((void**)&xt, g_xt);
    cudaGetSymbolAddress((void**)&wq, g_wq);
    cudaGetSymbolAddress((void**)&wo, g_wo);

    cudaFuncSetAttribute(gemm_mma_tf32, cudaFuncAttributeMaxDynamicSharedMemorySize,
                         G_SMEM_BYTES);
    cudaFuncSetAttribute(flash_attn_tc, cudaFuncAttributeMaxDynamicSharedMemorySize,
                         FA_SMEM_BYTES);

    // staging: pre-round to tf32
    round_copy_tf32<<<(M_ * C_) / 1024, 256>>>(x, xt);
    round_copy_tf32<<<(3 * C_ * C_) / 1024, 256>>>(w_qkv, wq);
    round_copy_tf32<<<(C_ * C_) / 1024, 256>>>(w_out, wo);

    // 1) qkv = x @ w_qkv
    dim3 g1(3 * C_ / GBN, M_ / GBM);
    gemm_mma_tf32<<<g1, 256, G_SMEM_BYTES>>>(xt, wq, qkv, M_, 3 * C_, C_);

    // 2) rope + split into Q,K,V [B,H,T,D] (tf32-rounded)
    const int nrope = B_ * T_ * H_ * 64;
    rope_split_kernel<<<nrope / 256, 256>>>(qkv, q, k, v);

    // 3) pipelined tensor-core causal flash attention -> y [B,T,C]
    dim3 g2(T_ / 128, H_, B_);
    flash_attn_tc<<<g2, 256, FA_SMEM_BYTES>>>(q, k, v, y);

    // 4) out = y @ w_out
    dim3 g3(C_ / GBN, M_ / GBM);
    gemm_mma_tf32<<<g3, 256, G_SMEM_BYTES>>>(y, wo, out, M_, C_, C_);
}

// round 9
// speedup vs baseline: 3.2712x; 1.1087x over previous
#include <cuda_runtime.h>
#include <math.h>
#include <stdint.h>

#define B_ 2
#define T_ 2048
#define C_ 2048
#define H_ 16
#define D_ 128
#define M_ (B_*T_)   // 4096

// ---------------- scratch (device globals; no allocation allowed) ----------------
__device__ float g_qkv[M_ * 3 * C_];           // [4096, 6144] natural
__device__ float g_q[B_ * H_ * T_ * D_];       // [B,H,T,D] (tf32-rounded)
__device__ float g_k[B_ * H_ * T_ * D_];
__device__ float g_v[B_ * H_ * T_ * D_];
__device__ float g_y[M_ * C_];                 // attention out, k-permuted tf32
__device__ float g_xt[M_ * C_];                // x, k-permuted tf32
__device__ float g_wq[3 * C_ * C_];            // w_qkv^T [6144][2048], k-permuted tf32
__device__ float g_wo[C_ * C_];                // w_out^T [2048][2048], k-permuted tf32

// ============================ PTX helpers ========================================
__device__ __forceinline__ uint32_t smem_u32(const void* p) {
    return (uint32_t)__cvta_generic_to_shared(p);
}
__device__ __forceinline__ uint32_t tf32b(float x) {   // fp32 -> tf32 bits, rna
    uint32_t u;
    asm("cvt.rna.tf32.f32 %0, %1;" : "=r"(u) : "f"(x));
    return u;
}
__device__ __forceinline__ float tf32f(float x) { return __uint_as_float(tf32b(x)); }

__device__ __forceinline__ void cp_async16(uint32_t s, const void* g) {
    asm volatile("cp.async.cg.shared.global [%0], [%1], 16;" :: "r"(s), "l"(g));
}
#define CP_ASYNC_COMMIT() asm volatile("cp.async.commit_group;" ::: "memory")
#define CP_ASYNC_WAIT1()  asm volatile("cp.async.wait_group 1;" ::: "memory")
#define CP_ASYNC_WAIT0()  asm volatile("cp.async.wait_group 0;" ::: "memory")

__device__ __forceinline__ void mma_tf32(float* d, const uint32_t* a, const uint32_t* b) {
    asm volatile(
        "mma.sync.aligned.m16n8k8.row.col.f32.tf32.tf32.f32 "
        "{%0,%1,%2,%3}, {%4,%5,%6,%7}, {%8,%9}, {%0,%1,%2,%3};"
        : "+f"(d[0]), "+f"(d[1]), "+f"(d[2]), "+f"(d[3])
        : "r"(a[0]), "r"(a[1]), "r"(a[2]), "r"(a[3]), "r"(b[0]), "r"(b[1]));
}

// ===== tensor-core tf32 GEMM v2: C[M,N] = A[M,K] @ Bt[N,K]^T, k-permuted inputs ==
// Block 128x128, BK=32, 8 warps (4x2), warp tile 32x64.
// Both tiles k-major [row][40]; all fragment loads are conflict-free LDS.64.
#define GSTR 40
#define GBUF (128*GSTR)                       // 5120 floats per tile
#define G_SMEM_BYTES (4*GBUF*4)               // 81920 B (A0,A1,B0,B1)

__global__ __launch_bounds__(256, 2)
void gemm_mma_tf32(const float* __restrict__ A, const float* __restrict__ Bt,
                   float* __restrict__ Cm, int M, int N, int K) {
    extern __shared__ __align__(16) float sm[];
    float* Asm = sm;               // [2][GBUF]
    float* Bsm = sm + 2 * GBUF;    // [2][GBUF]

    const int tid = threadIdx.x;
    const int wid = tid >> 5, lane = tid & 31;
    const int g = lane >> 2, tg = lane & 3;
    const int warp_m = (wid >> 1) * 32;
    const int warp_n = (wid & 1) * 64;
    const int m0 = blockIdx.y * 128;
    const int n0 = blockIdx.x * 128;

    const uint32_t aS = smem_u32(Asm);
    const uint32_t bS = smem_u32(Bsm);

    float acc[2][8][4];
    #pragma unroll
    for (int i = 0; i < 2; i++)
        #pragma unroll
        for (int j = 0; j < 8; j++)
            #pragma unroll
            for (int q = 0; q < 4; q++) acc[i][j][q] = 0.f;

    const int ntiles = K >> 5;

    auto load_tile = [&](int kt, int buf) {
        const int kbase = kt << 5;
        const uint32_t aDst = aS + buf * GBUF * 4;
        const uint32_t bDst = bS + buf * GBUF * 4;
        #pragma unroll
        for (int u = 0; u < 4; u++) {          // A: 128 rows x 32 fl = 1024 chunks
            const int e = u * 256 + tid;
            const int row = e >> 3, c4 = e & 7;
            cp_async16(aDst + (row * GSTR + c4 * 4) * 4,
                       A + (size_t)(m0 + row) * K + kbase + c4 * 4);
        }
        #pragma unroll
        for (int u = 0; u < 4; u++) {          // B: 128 rows x 32 fl
            const int e = u * 256 + tid;
            const int row = e >> 3, c4 = e & 7;
            cp_async16(bDst + (row * GSTR + c4 * 4) * 4,
                       Bt + (size_t)(n0 + row) * K + kbase + c4 * 4);
        }
        CP_ASYNC_COMMIT();
    };

    load_tile(0, 0);

    for (int kt = 0; kt < ntiles; kt++) {
        const int buf = kt & 1;
        if (kt + 1 < ntiles) {
            load_tile(kt + 1, buf ^ 1);
            CP_ASYNC_WAIT1();
        } else {
            CP_ASYNC_WAIT0();
        }
        __syncthreads();

        const float* As = Asm + buf * GBUF;
        const float* Bs = Bsm + buf * GBUF;

        #pragma unroll
        for (int kk8 = 0; kk8 < 4; kk8++) {
            const int kb = kk8 * 8 + tg * 2;
            uint32_t afr[2][4], bfr[8][2];
            #pragma unroll
            for (int mt = 0; mt < 2; mt++) {
                const int r = warp_m + mt * 16 + g;
                float2 lo = *(const float2*)&As[r * GSTR + kb];
                float2 hi = *(const float2*)&As[(r + 8) * GSTR + kb];
                afr[mt][0] = __float_as_uint(lo.x);
                afr[mt][1] = __float_as_uint(hi.x);
                afr[mt][2] = __float_as_uint(lo.y);
                afr[mt][3] = __float_as_uint(hi.y);
            }
            #pragma unroll
            for (int nt = 0; nt < 8; nt++) {
                const int c = warp_n + nt * 8 + g;
                float2 bb = *(const float2*)&Bs[c * GSTR + kb];
                bfr[nt][0] = __float_as_uint(bb.x);
                bfr[nt][1] = __float_as_uint(bb.y);
            }
            #pragma unroll
            for (int mt = 0; mt < 2; mt++)
                #pragma unroll
                for (int nt = 0; nt < 8; nt++)
                    mma_tf32(acc[mt][nt], afr[mt], bfr[nt]);
        }
        __syncthreads();
    }

    #pragma unroll
    for (int mt = 0; mt < 2; mt++) {
        const int r = m0 + warp_m + mt * 16 + g;
        #pragma unroll
        for (int nt = 0; nt < 8; nt++) {
            const int c = n0 + warp_n + nt * 8 + tg * 2;
            *(float2*)(Cm + (size_t)r * N + c)       = make_float2(acc[mt][nt][0], acc[mt][nt][1]);
            *(float2*)(Cm + (size_t)(r + 8) * N + c) = make_float2(acc[mt][nt][2], acc[mt][nt][3]);
        }
    }
}

// --------- staging: tf32 round + k-group permutation [0,4,1,5,2,6,3,7] ----------
__global__ void round_perm_copy(const float* __restrict__ in, float* __restrict__ out) {
    const int i = (blockIdx.x * blockDim.x + threadIdx.x) * 8;
    float4 v0 = *(const float4*)(in + i);
    float4 v1 = *(const float4*)(in + i + 4);
    *(float4*)(out + i)     = make_float4(tf32f(v0.x), tf32f(v1.x), tf32f(v0.y), tf32f(v1.y));
    *(float4*)(out + i + 4) = make_float4(tf32f(v0.z), tf32f(v1.z), tf32f(v0.w), tf32f(v1.w));
}

// W[K,N] -> WT[N,K] transposed + tf32-rounded + k-permuted
__global__ void transpose_perm_tf32(const float* __restrict__ W, float* __restrict__ WT,
                                    int K, int N) {
    __shared__ float tile[32][33];
    const int kb = blockIdx.y * 32, nb = blockIdx.x * 32;
    const int tx = threadIdx.x & 31, ty = threadIdx.x >> 5;
    #pragma unroll
    for (int r = ty; r < 32; r += 8)
        tile[r][tx] = W[(size_t)(kb + r) * N + nb + tx];
    __syncthreads();
    const int kperm = (tx & ~7) + ((tx & 3) << 1) + ((tx >> 2) & 1);
    #pragma unroll
    for (int r = ty; r < 32; r += 8)
        WT[(size_t)(nb + r) * K + kb + kperm] = tf32f(tile[tx][r]);
}

// ---------------- RoPE + split + fold 1/sqrt(D) into Q, tf32-round outputs ------
__global__ void rope_split_kernel(const float* __restrict__ qkv,
                                  float* __restrict__ Qo, float* __restrict__ Ko,
                                  float* __restrict__ Vo) {
    int idx = blockIdx.x * blockDim.x + threadIdx.x;
    if (idx >= B_ * T_ * H_ * 64) return;
    const int i = idx & 63;
    const int h = (idx >> 6) & 15;
    const int t = (idx >> 10) & (T_ - 1);
    const int b = idx >> 21;

    const float* row = qkv + (size_t)(b * T_ + t) * (3 * C_);
    const float inv = powf(10000.f, -(float)i / 64.f);
    const float f = (float)t * inv;
    float s, c;
    sincosf(f, &s, &c);

    const float q0 = row[h * D_ + i],            q1 = row[h * D_ + i + 64];
    const float k0 = row[C_ + h * D_ + i],       k1 = row[C_ + h * D_ + i + 64];
    const float v0 = row[2 * C_ + h * D_ + i],   v1 = row[2 * C_ + h * D_ + i + 64];

    const size_t o = ((size_t)(b * H_ + h) * T_ + t) * D_ + i;
    const float sc = 0.08838834764831845f;   // 1/sqrt(128)
    Qo[o]      = tf32f((q0 * c - q1 * s) * sc);
    Qo[o + 64] = tf32f((q1 * c + q0 * s) * sc);
    Ko[o]      = tf32f(k0 * c - k1 * s);
    Ko[o + 64] = tf32f(k1 * c + k0 * s);
    Vo[o]      = tf32f(v0);
    Vo[o + 64] = tf32f(v1);
}

// ============ tensor-core flash attention v2: cp.async pipeline ==================
#define QSTR 132
#define KSTR 132
#define PSTR 66
#define VSTR 136
#define FA_QOFF 0
#define FA_K0 (128*QSTR)
#define FA_K1 (FA_K0 + 64*KSTR)
#define FA_V0 (FA_K1 + 64*KSTR)
#define FA_V1 (FA_V0 + 64*VSTR)
#define FA_SMEM_FLOATS (FA_V1 + 64*VSTR)
#define FA_SMEM_BYTES (FA_SMEM_FLOATS * 4)   // 204800

__global__ __launch_bounds__(256, 1)
void flash_attn_tc(const float* __restrict__ Qg, const float* __restrict__ Kg,
                   const float* __restrict__ Vg, float* __restrict__ Yg) {
    extern __shared__ __align__(16) float sm[];
    float* Qs = sm + FA_QOFF;

    const int tid = threadIdx.x;
    const int w = tid >> 5, lane = tid & 31;
    const int g = lane >> 2, tg = lane & 3;

    const int qi = gridDim.x - 1 - blockIdx.x;   // heavy blocks first
    const int h = blockIdx.y;
    const int b = blockIdx.z;
    const size_t bh = (size_t)(b * H_ + h);
    const float* Qp = Qg + bh * T_ * D_ + (size_t)qi * 128 * D_;
    const float* Kb = Kg + bh * T_ * D_;
    const float* Vb = Vg + bh * T_ * D_;

    const uint32_t smB = smem_u32(sm);
    const uint32_t kOff[2] = {smB + FA_K0 * 4, smB + FA_K1 * 4};
    const uint32_t vOff[2] = {smB + FA_V0 * 4, smB + FA_V1 * 4};

    #pragma unroll
    for (int u = 0; u < 16; u++) {
        const int e = u * 256 + tid;
        const int r = e >> 5, c4 = e & 31;
        cp_async16(smB + (FA_QOFF + r * QSTR + c4 * 4) * 4, Qp + r * D_ + c4 * 4);
    }

    auto load_kv = [&](int chunk, int buf) {
        const float* Kc = Kb + (size_t)chunk * 64 * D_;
        const float* Vc = Vb + (size_t)chunk * 64 * D_;
        #pragma unroll
        for (int u = 0; u < 8; u++) {
            const int e = u * 256 + tid;
            const int r = e >> 5, c4 = e & 31;
            cp_async16(kOff[buf] + (r * KSTR + c4 * 4) * 4, Kc + r * D_ + c4 * 4);
        }
        #pragma unroll
        for (int u = 0; u < 8; u++) {
            const int e = u * 256 + tid;
            const int r = e >> 5, c4 = e & 31;
            cp_async16(vOff[buf] + (r * VSTR + c4 * 4) * 4, Vc + r * D_ + c4 * 4);
        }
        CP_ASYNC_COMMIT();
    };

    load_kv(0, 0);

    const int row0 = w * 16 + g;
    const int nk = 2 * (qi + 1);

    float o[16][4];
    float m0 = -INFINITY, m1 = -INFINITY, l0 = 0.f, l1 = 0.f;
    #pragma unroll
    for (int nt = 0; nt < 16; nt++)
        #pragma unroll
        for (int q = 0; q < 4; q++) o[nt][q] = 0.f;

    for (int i = 0; i < nk; i++) {
        const int kb = i & 1;
        float* Ks = sm + (kb ? FA_K1 : FA_K0);
        float* Ps = Ks;
        float* Vs = sm + (kb ? FA_V1 : FA_V0);

        CP_ASYNC_WAIT0();
        __syncthreads();

        float s[8][4];
        #pragma unroll
        for (int nt = 0; nt < 8; nt++)
            #pragma unroll
            for (int q = 0; q < 4; q++) s[nt][q] = 0.f;

        #pragma unroll
        for (int kk = 0; kk < 16; kk++) {
            const int d0 = kk * 8;
            uint32_t a[4];
            a[0] = __float_as_uint(Qs[row0 * QSTR + d0 + tg]);
            a[1] = __float_as_uint(Qs[(row0 + 8) * QSTR + d0 + tg]);
            a[2] = __float_as_uint(Qs[row0 * QSTR + d0 + tg + 4]);
            a[3] = __float_as_uint(Qs[(row0 + 8) * QSTR + d0 + tg + 4]);
            #pragma unroll
            for (int nt = 0; nt < 8; nt++) {
                const int c = nt * 8 + g;
                uint32_t bf[2];
                bf[0] = __float_as_uint(Ks[c * KSTR + d0 + tg]);
                bf[1] = __float_as_uint(Ks[c * KSTR + d0 + tg + 4]);
                mma_tf32(s[nt], a, bf);
            }
        }

        if (i >= 2 * qi) {
            const int rg0 = qi * 128 + row0;
            const int cb = i * 64;
            #pragma unroll
            for (int nt = 0; nt < 8; nt++) {
                const int c0 = cb + nt * 8 + 2 * tg;
                if (c0 > rg0)         s[nt][0] = -INFINITY;
                if (c0 + 1 > rg0)     s[nt][1] = -INFINITY;
                if (c0 > rg0 + 8)     s[nt][2] = -INFINITY;
                if (c0 + 1 > rg0 + 8) s[nt][3] = -INFINITY;
            }
        }

        float ml0 = -INFINITY, ml1 = -INFINITY;
        #pragma unroll
        for (int nt = 0; nt < 8; nt++) {
            ml0 = fmaxf(ml0, fmaxf(s[nt][0], s[nt][1]));
            ml1 = fmaxf(ml1, fmaxf(s[nt][2], s[nt][3]));
        }
        #pragma unroll
        for (int off = 1; off <= 2; off <<= 1) {
            ml0 = fmaxf(ml0, __shfl_xor_sync(0xffffffffu, ml0, off));
            ml1 = fmaxf(ml1, __shfl_xor_sync(0xffffffffu, ml1, off));
        }
        const float mn0 = fmaxf(m0, ml0), mn1 = fmaxf(m1, ml1);
        const float al0 = __expf(m0 - mn0), al1 = __expf(m1 - mn1);
        m0 = mn0; m1 = mn1;

        float sl0 = 0.f, sl1 = 0.f;
        #pragma unroll
        for (int nt = 0; nt < 8; nt++) {
            const int c0 = nt * 8 + 2 * tg;
            float e0 = __expf(s[nt][0] - m0);
            float e1 = __expf(s[nt][1] - m0);
            float e2 = __expf(s[nt][2] - m1);
            float e3 = __expf(s[nt][3] - m1);
            sl0 += e0 + e1;
            sl1 += e2 + e3;
            *(float2*)&Ps[row0 * PSTR + c0] = make_float2(tf32f(e0), tf32f(e1));
            *(float2*)&Ps[(row0 + 8) * PSTR + c0] = make_float2(tf32f(e2), tf32f(e3));
        }
        #pragma unroll
        for (int off = 1; off <= 2; off <<= 1) {
            sl0 += __shfl_xor_sync(0xffffffffu, sl0, off);
            sl1 += __shfl_xor_sync(0xffffffffu, sl1, off);
        }
        l0 = l0 * al0 + sl0;
        l1 = l1 * al1 + sl1;

        if (i + 1 < nk) load_kv(i + 1, kb ^ 1);

        #pragma unroll
        for (int nt = 0; nt < 16; nt++) {
            o[nt][0] *= al0; o[nt][1] *= al0;
            o[nt][2] *= al1; o[nt][3] *= al1;
        }

        #pragma unroll
        for (int kk = 0; kk < 8; kk++) {
            const int k0 = kk * 8;
            uint32_t a[4];
            a[0] = __float_as_uint(Ps[row0 * PSTR + k0 + tg]);
            a[1] = __float_as_uint(Ps[(row0 + 8) * PSTR + k0 + tg]);
            a[2] = __float_as_uint(Ps[row0 * PSTR + k0 + tg + 4]);
            a[3] = __float_as_uint(Ps[(row0 + 8) * PSTR + k0 + tg + 4]);
            #pragma unroll
            for (int nt = 0; nt < 16; nt++) {
                const int c = nt * 8 + g;
                uint32_t bf[2];
                bf[0] = __float_as_uint(Vs[(k0 + tg) * VSTR + c]);
                bf[1] = __float_as_uint(Vs[(k0 + tg + 4) * VSTR + c]);
                mma_tf32(o[nt], a, bf);
            }
        }
    }

    // ---- epilogue: normalize, tf32-round, write y k-PERMUTED for proj GEMM ----
    const float inv0 = 1.0f / l0, inv1 = 1.0f / l1;
    const int gr0 = qi * 128 + row0;
    // within-8 positions for elements (2tg, 2tg+1): p0 = ((2tg)&3)*2 + (tg>>1)
    const int p0 = ((2 * tg) & 3) * 2 + (tg >> 1);
    #pragma unroll
    for (int nt = 0; nt < 16; nt++) {
        const int gb = h * D_ + nt * 8;
        float* y0 = Yg + ((size_t)b * T_ + gr0) * C_ + gb;
        float* y1 = Yg + ((size_t)b * T_ + gr0 + 8) * C_ + gb;
        y0[p0]     = tf32f(o[nt][0] * inv0);
        y0[p0 + 2] = tf32f(o[nt][1] * inv0);
        y1[p0]     = tf32f(o[nt][2] * inv1);
        y1[p0 + 2] = tf32f(o[nt][3] * inv1);
    }
}

// ------------------------------------ launch -------------------------------------
extern "C" void kernel_launch(void* const* d_in, const int* in_sizes, int n_in,
                              void* d_out, int out_size) {
    const float* x     = (const float*)d_in[0];
    const float* w_qkv = (const float*)d_in[1];
    const float* w_out = (const float*)d_in[2];
    float* out = (float*)d_out;

    float *qkv, *q, *k, *v, *y, *xt, *wq, *wo;
    cudaGetSymbolAddress((void**)&qkv, g_qkv);
    cudaGetSymbolAddress((void**)&q, g_q);
    cudaGetSymbolAddress((void**)&k, g_k);
    cudaGetSymbolAddress((void**)&v, g_v);
    cudaGetSymbolAddress((void**)&y, g_y);
    cudaGetSymbolAddress((void**)&xt, g_xt);
    cudaGetSymbolAddress((void**)&wq, g_wq);
    cudaGetSymbolAddress((void**)&wo, g_wo);

    cudaFuncSetAttribute(gemm_mma_tf32, cudaFuncAttributeMaxDynamicSharedMemorySize,
                         G_SMEM_BYTES);
    cudaFuncSetAttribute(flash_attn_tc, cudaFuncAttributeMaxDynamicSharedMemorySize,
                         FA_SMEM_BYTES);

    // staging: tf32 round + k-permute (x) / transpose + permute (weights)
    round_perm_copy<<<(M_ * C_) / 2048, 256>>>(x, xt);
    transpose_perm_tf32<<<dim3(3 * C_ / 32, C_ / 32), 256>>>(w_qkv, wq, C_, 3 * C_);
    transpose_perm_tf32<<<dim3(C_ / 32, C_ / 32), 256>>>(w_out, wo, C_, C_);

    // 1) qkv = x @ w_qkv
    dim3 g1(3 * C_ / 128, M_ / 128);
    gemm_mma_tf32<<<g1, 256, G_SMEM_BYTES>>>(xt, wq, qkv, M_, 3 * C_, C_);

    // 2) rope + split into Q,K,V [B,H,T,D] (tf32-rounded)
    const int nrope = B_ * T_ * H_ * 64;
    rope_split_kernel<<<nrope / 256, 256>>>(qkv, q, k, v);

    // 3) pipelined tensor-core causal flash attention -> y (k-permuted)
    dim3 g2(T_ / 128, H_, B_);
    flash_attn_tc<<<g2, 256, FA_SMEM_BYTES>>>(q, k, v, y);

    // 4) out = y @ w_out
    dim3 g3(C_ / 128, M_ / 128);
    gemm_mma_tf32<<<g3, 256, G_SMEM_BYTES>>>(y, wo, out, M_, C_, C_);
}